// round 5
// baseline (speedup 1.0000x reference)
#include <cuda_runtime.h>

// Problem: out = diag(W)[-256:] * ((W^T)^4 pad(x))[-256:]
// N = 8192, x has 1024 entries, 4 steps.
//
// Implemented as 4 column-parallel GEMVs (y = W^T c) with a deterministic
// two-phase reduction (no float atomics), plus a tiny diagonal-extract kernel.

#define NN      8192
#define INN     1024
#define OUTN    256
#define TPB     256          // threads per block; each thread owns 4 columns (float4)
#define JT      8            // 8 j-tiles * (256 threads * 4 floats) = 8192 columns
#define IT_FULL 128          // steps 2-4: 128 i-tiles of 64 rows
#define IT_IN   32           // step 1:    32 i-tiles of 32 rows (only 1024 rows live)

// Scratch (no cudaMalloc allowed): partial sums + ping-pong c vectors.
__device__ float g_partial[(size_t)IT_FULL * NN];   // 4 MB
__device__ float g_cbuf[2][NN];

// Each block computes, for its 1024-column tile, the partial dot over its
// row range: partial[it][j] = sum_{i in tile} W[i][j] * c[i].
__global__ void __launch_bounds__(TPB)
gemv_partial_kernel(const float* __restrict__ W,
                    const float* __restrict__ c,
                    float* __restrict__ partial,
                    int rows_per_tile)
{
    const int jt = blockIdx.x;
    const int it = blockIdx.y;
    const int j  = jt * (TPB * 4) + threadIdx.x * 4;
    const int i0 = it * rows_per_tile;

    const float4* __restrict__ Wp =
        reinterpret_cast<const float4*>(W + (size_t)i0 * NN + j);
    const size_t stride4 = NN / 4;   // float4 row stride

    float4 acc = make_float4(0.f, 0.f, 0.f, 0.f);

    #pragma unroll 2
    for (int r = 0; r < rows_per_tile; r += 4) {
        const float4 cv = *reinterpret_cast<const float4*>(c + i0 + r);
        const float4 w0 = Wp[(size_t)(r + 0) * stride4];
        const float4 w1 = Wp[(size_t)(r + 1) * stride4];
        const float4 w2 = Wp[(size_t)(r + 2) * stride4];
        const float4 w3 = Wp[(size_t)(r + 3) * stride4];

        acc.x = fmaf(w0.x, cv.x, acc.x);
        acc.y = fmaf(w0.y, cv.x, acc.y);
        acc.z = fmaf(w0.z, cv.x, acc.z);
        acc.w = fmaf(w0.w, cv.x, acc.w);

        acc.x = fmaf(w1.x, cv.y, acc.x);
        acc.y = fmaf(w1.y, cv.y, acc.y);
        acc.z = fmaf(w1.z, cv.y, acc.z);
        acc.w = fmaf(w1.w, cv.y, acc.w);

        acc.x = fmaf(w2.x, cv.z, acc.x);
        acc.y = fmaf(w2.y, cv.z, acc.y);
        acc.z = fmaf(w2.z, cv.z, acc.z);
        acc.w = fmaf(w2.w, cv.z, acc.w);

        acc.x = fmaf(w3.x, cv.w, acc.x);
        acc.y = fmaf(w3.y, cv.w, acc.y);
        acc.z = fmaf(w3.z, cv.w, acc.z);
        acc.w = fmaf(w3.w, cv.w, acc.w);
    }

    reinterpret_cast<float4*>(partial + (size_t)it * NN + j)[0] = acc;
}

// Deterministic reduction of the i-tile partials: y[j] = sum_t partial[t][j].
// 2048 threads, each owning one float4 column group. Fixed summation order
// -> bitwise-identical result on every graph replay.
__global__ void __launch_bounds__(TPB)
reduce_kernel(const float4* __restrict__ partial,
              float4* __restrict__ out,
              int ntiles)
{
    const int j4 = blockIdx.x * blockDim.x + threadIdx.x;   // 0..2047
    float4 s = make_float4(0.f, 0.f, 0.f, 0.f);
    for (int t = 0; t < ntiles; ++t) {
        const float4 p = partial[(size_t)t * (NN / 4) + j4];
        s.x += p.x; s.y += p.y; s.z += p.z; s.w += p.w;
    }
    out[j4] = s;
}

// out[k] = W[d][d] * c[d], d = NN - OUTN + k
__global__ void extract_kernel(const float* __restrict__ W,
                               const float* __restrict__ c,
                               float* __restrict__ out)
{
    const int k = threadIdx.x;
    const int d = NN - OUTN + k;
    out[k] = W[(size_t)d * NN + d] * c[d];
}

extern "C" void kernel_launch(void* const* d_in, const int* in_sizes, int n_in,
                              void* d_out, int out_size)
{
    const float* x = (const float*)d_in[0];   // [1, 1024] float32
    const float* W = (const float*)d_in[1];   // [8192, 8192] float32
    // d_in[2] = num_steps (always 4 per setup_inputs); graph structure is static.
    float* out = (float*)d_out;               // [256] float32

    float* partial = nullptr;
    float* cbase   = nullptr;
    cudaGetSymbolAddress((void**)&partial, g_partial);
    cudaGetSymbolAddress((void**)&cbase,   g_cbuf);
    float* c0 = cbase;         // g_cbuf[0]
    float* c1 = cbase + NN;    // g_cbuf[1]

    const dim3 grid_in (JT, IT_IN);    //  256 blocks, 32 rows each (rows 0..1023)
    const dim3 grid_full(JT, IT_FULL); // 1024 blocks, 64 rows each
    const int reduce_blocks = NN / (TPB * 4);  // 8

    // Step 1: c0 = W^T pad(x)  — only first 1024 rows of W contribute.
    gemv_partial_kernel<<<grid_in, TPB>>>(W, x, partial, INN / IT_IN);
    reduce_kernel<<<reduce_blocks, TPB>>>((const float4*)partial, (float4*)c0, IT_IN);

    // Step 2: c1 = W^T c0
    gemv_partial_kernel<<<grid_full, TPB>>>(W, c0, partial, NN / IT_FULL);
    reduce_kernel<<<reduce_blocks, TPB>>>((const float4*)partial, (float4*)c1, IT_FULL);

    // Step 3: c0 = W^T c1
    gemv_partial_kernel<<<grid_full, TPB>>>(W, c1, partial, NN / IT_FULL);
    reduce_kernel<<<reduce_blocks, TPB>>>((const float4*)partial, (float4*)c0, IT_FULL);

    // Step 4: c1 = W^T c0
    gemv_partial_kernel<<<grid_full, TPB>>>(W, c0, partial, NN / IT_FULL);
    reduce_kernel<<<reduce_blocks, TPB>>>((const float4*)partial, (float4*)c1, IT_FULL);

    // out[k] = W[d][d] * c4[d]
    extract_kernel<<<1, OUTN>>>(W, c1, out);
}

// round 8
// speedup vs baseline: 1.2992x; 1.2992x over previous
#include <cuda_runtime.h>

// Problem: out = diag(W)[-256:] * ((W^T)^4 pad(x))[-256:]
// N = 8192, x has 1024 live entries, 4 steps.
//
// 4 column-parallel GEMVs (y = W^T c), deterministic two-phase reduction
// (fixed summation order, no float atomics), tiny diagonal-extract kernel.

#define NN      8192
#define INN     1024
#define OUTN    256
#define TPB     256          // gemv: each thread owns 4 columns (float4)
#define JT      8            // 8 j-tiles * (256*4) = 8192 columns
#define IT_FULL 128          // steps 2-4: 128 i-tiles of 64 rows
#define IT_IN   32           // step 1:    32 i-tiles of 32 rows (rows 0..1023)

// Scratch (no cudaMalloc allowed): partial sums + ping-pong c vectors.
__device__ float g_partial[(size_t)IT_FULL * NN];   // 4 MB
__device__ float g_cbuf[2][NN];

// Each block computes, for its 1024-column tile, the partial dot over its
// row range: partial[it][j] = sum_{i in tile} W[i][j] * c[i].
__global__ void __launch_bounds__(TPB)
gemv_partial_kernel(const float* __restrict__ W,
                    const float* __restrict__ c,
                    float* __restrict__ partial,
                    int rows_per_tile)
{
    const int jt = blockIdx.x;
    const int it = blockIdx.y;
    const int j  = jt * (TPB * 4) + threadIdx.x * 4;
    const int i0 = it * rows_per_tile;

    const float4* __restrict__ Wp =
        reinterpret_cast<const float4*>(W + (size_t)i0 * NN + j);
    const size_t stride4 = NN / 4;   // float4 row stride

    float4 acc = make_float4(0.f, 0.f, 0.f, 0.f);

    #pragma unroll 2
    for (int r = 0; r < rows_per_tile; r += 4) {
        const float4 cv = *reinterpret_cast<const float4*>(c + i0 + r);
        const float4 w0 = Wp[(size_t)(r + 0) * stride4];
        const float4 w1 = Wp[(size_t)(r + 1) * stride4];
        const float4 w2 = Wp[(size_t)(r + 2) * stride4];
        const float4 w3 = Wp[(size_t)(r + 3) * stride4];

        acc.x = fmaf(w0.x, cv.x, acc.x);
        acc.y = fmaf(w0.y, cv.x, acc.y);
        acc.z = fmaf(w0.z, cv.x, acc.z);
        acc.w = fmaf(w0.w, cv.x, acc.w);

        acc.x = fmaf(w1.x, cv.y, acc.x);
        acc.y = fmaf(w1.y, cv.y, acc.y);
        acc.z = fmaf(w1.z, cv.y, acc.z);
        acc.w = fmaf(w1.w, cv.y, acc.w);

        acc.x = fmaf(w2.x, cv.z, acc.x);
        acc.y = fmaf(w2.y, cv.z, acc.y);
        acc.z = fmaf(w2.z, cv.z, acc.z);
        acc.w = fmaf(w2.w, cv.z, acc.w);

        acc.x = fmaf(w3.x, cv.w, acc.x);
        acc.y = fmaf(w3.y, cv.w, acc.y);
        acc.z = fmaf(w3.z, cv.w, acc.z);
        acc.w = fmaf(w3.w, cv.w, acc.w);
    }

    reinterpret_cast<float4*>(partial + (size_t)it * NN + j)[0] = acc;
}

// Parallel deterministic reduction: y[j] = sum_t partial[t][j].
// Grid = 64 blocks; each block owns 128 columns (32 float4 groups).
// Threads: 32 column-groups x 8 tile-slices. Each thread sums tiles
// t = slice, slice+8, ... (independent loads -> high MLP), then slice
// partials are combined in fixed sequential order via smem. The summation
// tree is identical on every launch -> bitwise-deterministic.
__global__ void __launch_bounds__(TPB)
reduce_kernel(const float4* __restrict__ partial,
              float4* __restrict__ out,
              int ntiles)
{
    __shared__ float4 sm[TPB];
    const int jg = threadIdx.x & 31;          // column group within block
    const int ts = threadIdx.x >> 5;          // tile slice 0..7
    const int j4 = blockIdx.x * 32 + jg;      // global float4 column index

    float4 s = make_float4(0.f, 0.f, 0.f, 0.f);
    #pragma unroll 4
    for (int t = ts; t < ntiles; t += 8) {
        const float4 p = partial[(size_t)t * (NN / 4) + j4];
        s.x += p.x; s.y += p.y; s.z += p.z; s.w += p.w;
    }
    sm[threadIdx.x] = s;
    __syncthreads();

    if (ts == 0) {
        float4 acc = sm[jg];
        #pragma unroll
        for (int k = 1; k < 8; ++k) {
            const float4 p = sm[k * 32 + jg];
            acc.x += p.x; acc.y += p.y; acc.z += p.z; acc.w += p.w;
        }
        out[j4] = acc;
    }
}

// out[k] = W[d][d] * c[d], d = NN - OUTN + k
__global__ void extract_kernel(const float* __restrict__ W,
                               const float* __restrict__ c,
                               float* __restrict__ out)
{
    const int k = threadIdx.x;
    const int d = NN - OUTN + k;
    out[k] = W[(size_t)d * NN + d] * c[d];
}

extern "C" void kernel_launch(void* const* d_in, const int* in_sizes, int n_in,
                              void* d_out, int out_size)
{
    const float* x = (const float*)d_in[0];   // [1, 1024] float32
    const float* W = (const float*)d_in[1];   // [8192, 8192] float32
    // d_in[2] = num_steps (always 4 per setup_inputs); graph structure static.
    float* out = (float*)d_out;               // [256] float32

    float* partial = nullptr;
    float* cbase   = nullptr;
    cudaGetSymbolAddress((void**)&partial, g_partial);
    cudaGetSymbolAddress((void**)&cbase,   g_cbuf);
    float* c0 = cbase;         // g_cbuf[0]
    float* c1 = cbase + NN;    // g_cbuf[1]

    const dim3 grid_in  (JT, IT_IN);    //  256 blocks, 32 rows each
    const dim3 grid_full(JT, IT_FULL);  // 1024 blocks, 64 rows each
    const int reduce_blocks = NN / 128; // 64 blocks x 128 columns

    // Step 1: c0 = W^T pad(x)  — only first 1024 rows of W contribute.
    gemv_partial_kernel<<<grid_in, TPB>>>(W, x, partial, INN / IT_IN);
    reduce_kernel<<<reduce_blocks, TPB>>>((const float4*)partial, (float4*)c0, IT_IN);

    // Step 2: c1 = W^T c0
    gemv_partial_kernel<<<grid_full, TPB>>>(W, c0, partial, NN / IT_FULL);
    reduce_kernel<<<reduce_blocks, TPB>>>((const float4*)partial, (float4*)c1, IT_FULL);

    // Step 3: c0 = W^T c1
    gemv_partial_kernel<<<grid_full, TPB>>>(W, c1, partial, NN / IT_FULL);
    reduce_kernel<<<reduce_blocks, TPB>>>((const float4*)partial, (float4*)c0, IT_FULL);

    // Step 4: c1 = W^T c0
    gemv_partial_kernel<<<grid_full, TPB>>>(W, c0, partial, NN / IT_FULL);
    reduce_kernel<<<reduce_blocks, TPB>>>((const float4*)partial, (float4*)c1, IT_FULL);

    // out[k] = W[d][d] * c4[d]
    extract_kernel<<<1, OUTN>>>(W, c1, out);
}

// round 10
// speedup vs baseline: 1.7096x; 1.3159x over previous
#include <cuda_runtime.h>

// Problem: out = diag(W)[-256:] * ((W^T)^4 pad(x))[-256:]
// N = 8192, x has 1024 live entries, 4 steps.
//
// Traffic-minimal plan (all fp32, deterministic fixed-order reductions):
//   step 1: c0 = W^T pad(x)      -> only W rows 0..1023      (32 MB)
//   step 2: c1 = W^T c0          -> full W                   (256 MB)
//   step 3: c0 = W^T c1          -> full W                   (256 MB)
//   step 4: out = diag * (W^T c0)[-256:] -> only last 256 W columns (8 MB)

#define NN      8192
#define INN     1024
#define OUTN    256
#define TPB     256
#define JT      8            // 8 j-tiles * (256*4) = 8192 columns
#define IT_FULL 128          // full steps: 128 i-tiles of 64 rows
#define IT_IN   32           // step 1: 32 i-tiles of 32 rows
#define IT_S4   128          // step 4: 128 i-tiles of 64 rows

// Scratch (no cudaMalloc allowed).
__device__ float g_partial[(size_t)IT_FULL * NN];   // 4 MB (reused by step 4)
__device__ float g_cbuf[2][NN];

// partial[it][j] = sum_{i in tile it} W[i][j] * c[i], for a 1024-col j-tile.
__global__ void __launch_bounds__(TPB)
gemv_partial_kernel(const float* __restrict__ W,
                    const float* __restrict__ c,
                    float* __restrict__ partial,
                    int rows_per_tile)
{
    const int jt = blockIdx.x;
    const int it = blockIdx.y;
    const int j  = jt * (TPB * 4) + threadIdx.x * 4;
    const int i0 = it * rows_per_tile;

    const float4* __restrict__ Wp =
        reinterpret_cast<const float4*>(W + (size_t)i0 * NN + j);
    const size_t stride4 = NN / 4;

    float4 acc = make_float4(0.f, 0.f, 0.f, 0.f);

    #pragma unroll 2
    for (int r = 0; r < rows_per_tile; r += 4) {
        const float4 cv = *reinterpret_cast<const float4*>(c + i0 + r);
        const float4 w0 = Wp[(size_t)(r + 0) * stride4];
        const float4 w1 = Wp[(size_t)(r + 1) * stride4];
        const float4 w2 = Wp[(size_t)(r + 2) * stride4];
        const float4 w3 = Wp[(size_t)(r + 3) * stride4];

        acc.x = fmaf(w0.x, cv.x, acc.x);
        acc.y = fmaf(w0.y, cv.x, acc.y);
        acc.z = fmaf(w0.z, cv.x, acc.z);
        acc.w = fmaf(w0.w, cv.x, acc.w);

        acc.x = fmaf(w1.x, cv.y, acc.x);
        acc.y = fmaf(w1.y, cv.y, acc.y);
        acc.z = fmaf(w1.z, cv.y, acc.z);
        acc.w = fmaf(w1.w, cv.y, acc.w);

        acc.x = fmaf(w2.x, cv.z, acc.x);
        acc.y = fmaf(w2.y, cv.z, acc.y);
        acc.z = fmaf(w2.z, cv.z, acc.z);
        acc.w = fmaf(w2.w, cv.z, acc.w);

        acc.x = fmaf(w3.x, cv.w, acc.x);
        acc.y = fmaf(w3.y, cv.w, acc.y);
        acc.z = fmaf(w3.z, cv.w, acc.z);
        acc.w = fmaf(w3.w, cv.w, acc.w);
    }

    reinterpret_cast<float4*>(partial + (size_t)it * NN + j)[0] = acc;
}

// y[j] = sum_t partial[t][j]. 256 blocks; block = 8 float4 col-groups x 32
// tile-slices. Each thread sums ntiles/32 strided tiles (independent loads),
// then slice 0 combines the 32 slice sums in fixed sequential order via smem.
// Deterministic: identical summation tree every replay.
__global__ void __launch_bounds__(TPB)
reduce_kernel(const float4* __restrict__ partial,
              float4* __restrict__ out,
              int ntiles)
{
    __shared__ float4 sm[TPB];
    const int jg = threadIdx.x & 7;       // col group 0..7
    const int ts = threadIdx.x >> 3;      // tile slice 0..31
    const int j4 = blockIdx.x * 8 + jg;   // global float4 column

    float4 s = make_float4(0.f, 0.f, 0.f, 0.f);
    #pragma unroll 4
    for (int t = ts; t < ntiles; t += 32) {
        const float4 p = partial[(size_t)t * (NN / 4) + j4];
        s.x += p.x; s.y += p.y; s.z += p.z; s.w += p.w;
    }
    sm[threadIdx.x] = s;
    __syncthreads();

    if (ts == 0) {
        float4 acc = sm[jg];
        #pragma unroll
        for (int k = 1; k < 32; ++k) {
            const float4 p = sm[k * 8 + jg];
            acc.x += p.x; acc.y += p.y; acc.z += p.z; acc.w += p.w;
        }
        out[j4] = acc;
    }
}

// Step 4 phase A: only the last 256 columns of W are needed.
// partial[it][k] = sum_{i in tile} W[i][NN-OUTN+k] * c[i].
// Block = 64 float4 col-groups x 4 row-slices of 16 rows; 128 blocks.
__global__ void __launch_bounds__(TPB)
step4_partial_kernel(const float* __restrict__ W,
                     const float* __restrict__ c,
                     float* __restrict__ partial)
{
    __shared__ float4 sm[TPB];
    const int it = blockIdx.x;
    const int jg = threadIdx.x & 63;      // col group: col = NN-OUTN + jg*4
    const int rs = threadIdx.x >> 6;      // row slice 0..3
    const int i0 = it * 64 + rs * 16;

    const float4* __restrict__ Wp =
        reinterpret_cast<const float4*>(W + (size_t)i0 * NN + (NN - OUTN)) + jg;
    const size_t stride4 = NN / 4;

    float4 acc = make_float4(0.f, 0.f, 0.f, 0.f);
    #pragma unroll 4
    for (int r = 0; r < 16; ++r) {
        const float cv = c[i0 + r];
        const float4 w = Wp[(size_t)r * stride4];
        acc.x = fmaf(w.x, cv, acc.x);
        acc.y = fmaf(w.y, cv, acc.y);
        acc.z = fmaf(w.z, cv, acc.z);
        acc.w = fmaf(w.w, cv, acc.w);
    }
    sm[threadIdx.x] = acc;
    __syncthreads();

    if (rs == 0) {
        float4 a = sm[jg];
        #pragma unroll
        for (int k = 1; k < 4; ++k) {
            const float4 p = sm[k * 64 + jg];
            a.x += p.x; a.y += p.y; a.z += p.z; a.w += p.w;
        }
        reinterpret_cast<float4*>(partial + (size_t)it * OUTN)[jg] = a;
    }
}

// Step 4 phase B: out[k] = W[d][d] * sum_t partial[t][k], d = NN-OUTN+k.
// Fixed-order sum over 128 tiles; partial buffer is L2-resident.
__global__ void __launch_bounds__(OUTN)
step4_final_kernel(const float* __restrict__ W,
                   const float* __restrict__ partial,
                   float* __restrict__ out)
{
    const int k = threadIdx.x;
    float s = 0.f;
    #pragma unroll 8
    for (int t = 0; t < IT_S4; ++t)
        s += partial[(size_t)t * OUTN + k];
    const int d = NN - OUTN + k;
    out[k] = W[(size_t)d * NN + d] * s;
}

extern "C" void kernel_launch(void* const* d_in, const int* in_sizes, int n_in,
                              void* d_out, int out_size)
{
    const float* x = (const float*)d_in[0];   // [1, 1024] float32
    const float* W = (const float*)d_in[1];   // [8192, 8192] float32
    // d_in[2] = num_steps (always 4 per setup_inputs); graph structure static.
    float* out = (float*)d_out;               // [256] float32

    float* partial = nullptr;
    float* cbase   = nullptr;
    cudaGetSymbolAddress((void**)&partial, g_partial);
    cudaGetSymbolAddress((void**)&cbase,   g_cbuf);
    float* c0 = cbase;         // g_cbuf[0]
    float* c1 = cbase + NN;    // g_cbuf[1]

    const dim3 grid_in  (JT, IT_IN);    //  256 blocks, 32 rows each
    const dim3 grid_full(JT, IT_FULL);  // 1024 blocks, 64 rows each
    const int reduce_blocks = NN / 32;  // 256 blocks x 8 float4 cols

    // Step 1: c0 = W^T pad(x)  — only first 1024 rows of W contribute.
    gemv_partial_kernel<<<grid_in, TPB>>>(W, x, partial, INN / IT_IN);
    reduce_kernel<<<reduce_blocks, TPB>>>((const float4*)partial, (float4*)c0, IT_IN);

    // Step 2: c1 = W^T c0  (full W)
    gemv_partial_kernel<<<grid_full, TPB>>>(W, c0, partial, NN / IT_FULL);
    reduce_kernel<<<reduce_blocks, TPB>>>((const float4*)partial, (float4*)c1, IT_FULL);

    // Step 3: c0 = W^T c1  (full W)
    gemv_partial_kernel<<<grid_full, TPB>>>(W, c1, partial, NN / IT_FULL);
    reduce_kernel<<<reduce_blocks, TPB>>>((const float4*)partial, (float4*)c0, IT_FULL);

    // Step 4: out = diag(W)[-256:] * (W^T c0)[-256:] — only 256 W columns.
    step4_partial_kernel<<<IT_S4, TPB>>>(W, c0, partial);
    step4_final_kernel<<<1, OUTN>>>(W, partial, out);
}

// round 14
// speedup vs baseline: 1.8165x; 1.0625x over previous
#include <cuda_runtime.h>

// Problem: out = diag(W)[-256:] * ((W^T)^4 pad(x))[-256:]
// N = 8192, x has 1024 live entries, 4 steps.
//
// Traffic-minimal plan (all fp32, deterministic fixed-order reductions):
//   step 1: partialA = tiles of W^T pad(x)        (W rows 0..1023, 32 MB)
//   step 2: partialB = tiles of W^T c0            (full W, 256 MB; c0 reduced
//                                                  from partialA in-prologue)
//   step 3: partialA = tiles of W^T c1            (full W, 256 MB; c1 reduced
//                                                  from partialB in-prologue)
//   step 4: out = diag * (W^T c2)[-256:]          (last 256 W cols, 8 MB; c2
//                                                  reduced from partialA)
// 5 launches total; every cross-tile sum has a fixed order -> deterministic.

#define NN      8192
#define INN     1024
#define OUTN    256
#define TPB     256
#define JT      8            // 8 j-tiles * (256*4) = 8192 columns
#define IT_FULL 128          // full steps: 128 i-tiles of 64 rows
#define IT_IN   32           // step 1: 32 i-tiles of 32 rows
#define IT_S4   128          // step 4: 128 i-tiles of 64 rows

// Scratch (no cudaMalloc allowed). Ping-pong partial buffers.
__device__ float g_partialA[(size_t)IT_FULL * NN];   // 4 MB
__device__ float g_partialB[(size_t)IT_FULL * NN];   // 4 MB
__device__ float g_s4[(size_t)IT_S4 * OUTN];         // 128 KB

// ---------------------------------------------------------------------------
// Step 1: partial[it][j] = sum_{i in tile it} W[i][j] * x[i]  (x dense input)
// ---------------------------------------------------------------------------
__global__ void __launch_bounds__(TPB)
gemv_in_kernel(const float* __restrict__ W,
               const float* __restrict__ x,
               float* __restrict__ partial)
{
    const int jt = blockIdx.x;
    const int it = blockIdx.y;
    const int j  = jt * (TPB * 4) + threadIdx.x * 4;
    const int i0 = it * (INN / IT_IN);            // 32 rows per tile

    const float4* __restrict__ Wp =
        reinterpret_cast<const float4*>(W + (size_t)i0 * NN + j);
    const size_t stride4 = NN / 4;

    float4 acc = make_float4(0.f, 0.f, 0.f, 0.f);
    #pragma unroll 2
    for (int r = 0; r < INN / IT_IN; r += 4) {
        const float4 cv = *reinterpret_cast<const float4*>(x + i0 + r);
        const float4 w0 = Wp[(size_t)(r + 0) * stride4];
        const float4 w1 = Wp[(size_t)(r + 1) * stride4];
        const float4 w2 = Wp[(size_t)(r + 2) * stride4];
        const float4 w3 = Wp[(size_t)(r + 3) * stride4];
        acc.x = fmaf(w0.x, cv.x, acc.x); acc.y = fmaf(w0.y, cv.x, acc.y);
        acc.z = fmaf(w0.z, cv.x, acc.z); acc.w = fmaf(w0.w, cv.x, acc.w);
        acc.x = fmaf(w1.x, cv.y, acc.x); acc.y = fmaf(w1.y, cv.y, acc.y);
        acc.z = fmaf(w1.z, cv.y, acc.z); acc.w = fmaf(w1.w, cv.y, acc.w);
        acc.x = fmaf(w2.x, cv.z, acc.x); acc.y = fmaf(w2.y, cv.z, acc.y);
        acc.z = fmaf(w2.z, cv.z, acc.z); acc.w = fmaf(w2.w, cv.z, acc.w);
        acc.x = fmaf(w3.x, cv.w, acc.x); acc.y = fmaf(w3.y, cv.w, acc.y);
        acc.z = fmaf(w3.z, cv.w, acc.z); acc.w = fmaf(w3.w, cv.w, acc.w);
    }
    reinterpret_cast<float4*>(partial + (size_t)it * NN + j)[0] = acc;
}

// ---------------------------------------------------------------------------
// Fused full GEMV: prologue reduces c[i0..i0+63] from partial_in (ntiles
// tiles, fixed order), main loop streams 64 rows x 1024 cols of W.
// partial_out[it][j] = sum_{i in tile} W[i][j] * c[i].
// ---------------------------------------------------------------------------
__global__ void __launch_bounds__(TPB)
gemv_fused_kernel(const float* __restrict__ W,
                  const float* __restrict__ partial_in,
                  int ntiles_in,
                  float* __restrict__ partial_out)
{
    __shared__ float red[TPB];
    __shared__ __align__(16) float c_sm[64];

    const int jt = blockIdx.x;
    const int it = blockIdx.y;
    const int i0 = it * 64;

    // Prologue: c[i0+r] = sum_t partial_in[t][i0+r], deterministic order.
    {
        const int r = threadIdx.x & 63;
        const int s = threadIdx.x >> 6;          // slice 0..3
        const int tps = ntiles_in >> 2;          // tiles per slice
        float a = 0.f;
        const int tbeg = s * tps;
        for (int t = tbeg; t < tbeg + tps; ++t)
            a += partial_in[(size_t)t * NN + i0 + r];
        red[threadIdx.x] = a;
        __syncthreads();
        if (s == 0) {
            float v = red[r];
            v += red[64 + r];
            v += red[128 + r];
            v += red[192 + r];
            c_sm[r] = v;
        }
        __syncthreads();
    }

    // Main streaming loop.
    const int j = jt * (TPB * 4) + threadIdx.x * 4;
    const float4* __restrict__ Wp =
        reinterpret_cast<const float4*>(W + (size_t)i0 * NN + j);
    const size_t stride4 = NN / 4;

    float4 acc = make_float4(0.f, 0.f, 0.f, 0.f);
    #pragma unroll 2
    for (int r = 0; r < 64; r += 4) {
        const float4 cv = *reinterpret_cast<const float4*>(c_sm + r);
        const float4 w0 = Wp[(size_t)(r + 0) * stride4];
        const float4 w1 = Wp[(size_t)(r + 1) * stride4];
        const float4 w2 = Wp[(size_t)(r + 2) * stride4];
        const float4 w3 = Wp[(size_t)(r + 3) * stride4];
        acc.x = fmaf(w0.x, cv.x, acc.x); acc.y = fmaf(w0.y, cv.x, acc.y);
        acc.z = fmaf(w0.z, cv.x, acc.z); acc.w = fmaf(w0.w, cv.x, acc.w);
        acc.x = fmaf(w1.x, cv.y, acc.x); acc.y = fmaf(w1.y, cv.y, acc.y);
        acc.z = fmaf(w1.z, cv.y, acc.z); acc.w = fmaf(w1.w, cv.y, acc.w);
        acc.x = fmaf(w2.x, cv.z, acc.x); acc.y = fmaf(w2.y, cv.z, acc.y);
        acc.z = fmaf(w2.z, cv.z, acc.z); acc.w = fmaf(w2.w, cv.z, acc.w);
        acc.x = fmaf(w3.x, cv.w, acc.x); acc.y = fmaf(w3.y, cv.w, acc.y);
        acc.z = fmaf(w3.z, cv.w, acc.z); acc.w = fmaf(w3.w, cv.w, acc.w);
    }
    reinterpret_cast<float4*>(partial_out + (size_t)it * NN + j)[0] = acc;
}

// ---------------------------------------------------------------------------
// Step 4 phase A (fused): prologue reduces c[i0..i0+63] from partial_in
// (128 tiles), then computes the 256-column partial for this 64-row tile.
// s4[it][k] = sum_{i in tile} W[i][NN-OUTN+k] * c[i].
// ---------------------------------------------------------------------------
__global__ void __launch_bounds__(TPB)
step4_partial_kernel(const float* __restrict__ W,
                     const float* __restrict__ partial_in,
                     float* __restrict__ s4)
{
    __shared__ float red[TPB];
    __shared__ __align__(16) float c_sm[64];
    __shared__ float4 sm[TPB];

    const int it = blockIdx.x;
    const int i0 = it * 64;

    // Prologue reduction (128 tiles, fixed order).
    {
        const int r = threadIdx.x & 63;
        const int s = threadIdx.x >> 6;
        float a = 0.f;
        const int tbeg = s * 32;
        for (int t = tbeg; t < tbeg + 32; ++t)
            a += partial_in[(size_t)t * NN + i0 + r];
        red[threadIdx.x] = a;
        __syncthreads();
        if (s == 0) {
            float v = red[r];
            v += red[64 + r];
            v += red[128 + r];
            v += red[192 + r];
            c_sm[r] = v;
        }
        __syncthreads();
    }

    const int jg = threadIdx.x & 63;      // col group: col = NN-OUTN + jg*4
    const int rs = threadIdx.x >> 6;      // row slice 0..3 (16 rows each)
    const int ib = rs * 16;

    const float4* __restrict__ Wp =
        reinterpret_cast<const float4*>(W + (size_t)(i0 + ib) * NN + (NN - OUTN)) + jg;
    const size_t stride4 = NN / 4;

    float4 acc = make_float4(0.f, 0.f, 0.f, 0.f);
    #pragma unroll 4
    for (int r = 0; r < 16; ++r) {
        const float cv = c_sm[ib + r];
        const float4 w = Wp[(size_t)r * stride4];
        acc.x = fmaf(w.x, cv, acc.x);
        acc.y = fmaf(w.y, cv, acc.y);
        acc.z = fmaf(w.z, cv, acc.z);
        acc.w = fmaf(w.w, cv, acc.w);
    }
    sm[threadIdx.x] = acc;
    __syncthreads();

    if (rs == 0) {
        float4 a = sm[jg];
        #pragma unroll
        for (int k = 1; k < 4; ++k) {
            const float4 p = sm[k * 64 + jg];
            a.x += p.x; a.y += p.y; a.z += p.z; a.w += p.w;
        }
        reinterpret_cast<float4*>(s4 + (size_t)it * OUTN)[jg] = a;
    }
}

// Step 4 phase B: out[k] = W[d][d] * sum_t s4[t][k], d = NN-OUTN+k.
__global__ void __launch_bounds__(OUTN)
step4_final_kernel(const float* __restrict__ W,
                   const float* __restrict__ s4,
                   float* __restrict__ out)
{
    const int k = threadIdx.x;
    float s = 0.f;
    #pragma unroll 8
    for (int t = 0; t < IT_S4; ++t)
        s += s4[(size_t)t * OUTN + k];
    const int d = NN - OUTN + k;
    out[k] = W[(size_t)d * NN + d] * s;
}

extern "C" void kernel_launch(void* const* d_in, const int* in_sizes, int n_in,
                              void* d_out, int out_size)
{
    const float* x = (const float*)d_in[0];   // [1, 1024] float32
    const float* W = (const float*)d_in[1];   // [8192, 8192] float32
    // d_in[2] = num_steps (always 4 per setup_inputs); graph structure static.
    float* out = (float*)d_out;               // [256] float32

    float *pA = nullptr, *pB = nullptr, *s4 = nullptr;
    cudaGetSymbolAddress((void**)&pA, g_partialA);
    cudaGetSymbolAddress((void**)&pB, g_partialB);
    cudaGetSymbolAddress((void**)&s4, g_s4);

    const dim3 grid_in  (JT, IT_IN);    //  256 blocks, 32 rows each
    const dim3 grid_full(JT, IT_FULL);  // 1024 blocks, 64 rows each

    // Step 1: partialA = tiles of W^T pad(x)  (rows 0..1023 only).
    gemv_in_kernel<<<grid_in, TPB>>>(W, x, pA);

    // Step 2: partialB = tiles of W^T c0 (c0 reduced from partialA in-kernel).
    gemv_fused_kernel<<<grid_full, TPB>>>(W, pA, IT_IN, pB);

    // Step 3: partialA = tiles of W^T c1 (c1 reduced from partialB in-kernel).
    gemv_fused_kernel<<<grid_full, TPB>>>(W, pB, IT_FULL, pA);

    // Step 4: out = diag(W)[-256:] * (W^T c2)[-256:] — only 256 W columns.
    step4_partial_kernel<<<IT_S4, TPB>>>(W, pA, s4);
    step4_final_kernel<<<1, OUTN>>>(W, s4, out);
}